// round 11
// baseline (speedup 1.0000x reference)
#include <cuda_runtime.h>
#include <cstdint>

#define TT 512
#define BB_ 64
#define HH 512
#define II 256
#define NG 2048  // 4*H

#define NCTA_REC 128
#define REC_THREADS 256
#define REC_SMEM ((8192 + 1024) * 4)  // h tile 32KB + gates 4KB

// 256 MB scratch for the precomputed input projection (sanctioned __device__ scratch).
__device__ float g_xg[(size_t)TT * BB_ * NG];
__device__ unsigned g_arrive[4];  // one barrier counter per b-block group of 32 CTAs

static __device__ __forceinline__ unsigned ld_acq_gpu(unsigned* p) {
  unsigned v;
  asm volatile("ld.acquire.gpu.u32 %0, [%1];" : "=r"(v) : "l"(p) : "memory");
  return v;
}

static __device__ __forceinline__ float fast_sigmoid(float x) {
  return __fdividef(1.0f, 1.0f + __expf(-x));
}
static __device__ __forceinline__ float fast_tanh(float x) {
  float ax = fabsf(x);
  float e = __expf(-2.0f * ax);
  float r = __fdividef(1.0f - e, 1.0f + e);
  return copysignf(r, x);
}

// Packed dual-fp32 FMA (FFMA2): d = a*b + d elementwise on (lo,hi) pairs.
static __device__ __forceinline__ void fma2(unsigned long long& d,
                                            unsigned long long a,
                                            unsigned long long b) {
  asm("fma.rn.f32x2 %0, %1, %2, %0;" : "+l"(d) : "l"(a), "l"(b));
}

static __device__ __forceinline__ float2 unpack2(unsigned long long x) {
  float2 f;
  asm("mov.b64 {%0, %1}, %2;" : "=f"(f.x), "=f"(f.y) : "l"(x));
  return f;
}

static __device__ __forceinline__ unsigned long long pack2(float x, float y) {
  unsigned long long r;
  asm("mov.b64 %0, {%1, %2};" : "=l"(r) : "f"(x), "f"(y));
  return r;
}

// 128-bit shared load straight into two b64 (k,k+1) pairs.
static __device__ __forceinline__ void lds_v2u64(unsigned long long& a,
                                                 unsigned long long& b,
                                                 uint32_t addr) {
  asm("ld.shared.v2.u64 {%0, %1}, [%2];" : "=l"(a), "=l"(b) : "r"(addr));
}

// ---------------------------------------------------------------------------
// Phase 1: xg[t*B+b, n] = sum_k x[t,b,k] * w_ih[n,k] + b_ih[n] + b_hh[n]
// 128x128x16 SGEMM tile, 256 threads, 8x8 per-thread micro-tile.
// Also resets the grid-barrier counters so graph replays are deterministic.
// ---------------------------------------------------------------------------
__global__ __launch_bounds__(256) void xg_gemm_kernel(
    const float* __restrict__ x, const float* __restrict__ w_ih,
    const float* __restrict__ b_ih, const float* __restrict__ b_hh) {
  if (blockIdx.x == 0 && blockIdx.y == 0 && threadIdx.x < 4)
    g_arrive[threadIdx.x] = 0u;

  __shared__ float Asm[16][132];
  __shared__ float Bsm[16][132];

  const int tid = threadIdx.x;
  const int tx = tid & 15;
  const int ty = tid >> 4;
  const int m0 = blockIdx.y * 128;
  const int n0 = blockIdx.x * 128;

  float acc[8][8];
#pragma unroll
  for (int i = 0; i < 8; ++i)
#pragma unroll
    for (int j = 0; j < 8; ++j) acc[i][j] = 0.0f;

  for (int k0 = 0; k0 < II; k0 += 16) {
#pragma unroll
    for (int r = 0; r < 2; ++r) {
      int idx = tid + r * 256;
      int m = idx >> 2;
      int kq = idx & 3;
      float4 v = *reinterpret_cast<const float4*>(
          &x[(size_t)(m0 + m) * II + k0 + kq * 4]);
      Asm[kq * 4 + 0][m] = v.x; Asm[kq * 4 + 1][m] = v.y;
      Asm[kq * 4 + 2][m] = v.z; Asm[kq * 4 + 3][m] = v.w;
      float4 w = *reinterpret_cast<const float4*>(
          &w_ih[(size_t)(n0 + m) * II + k0 + kq * 4]);
      Bsm[kq * 4 + 0][m] = w.x; Bsm[kq * 4 + 1][m] = w.y;
      Bsm[kq * 4 + 2][m] = w.z; Bsm[kq * 4 + 3][m] = w.w;
    }
    __syncthreads();
#pragma unroll
    for (int kk = 0; kk < 16; ++kk) {
      float4 a0 = *reinterpret_cast<const float4*>(&Asm[kk][ty * 4]);
      float4 a1 = *reinterpret_cast<const float4*>(&Asm[kk][64 + ty * 4]);
      float4 q0 = *reinterpret_cast<const float4*>(&Bsm[kk][tx * 4]);
      float4 q1 = *reinterpret_cast<const float4*>(&Bsm[kk][64 + tx * 4]);
      float av[8] = {a0.x, a0.y, a0.z, a0.w, a1.x, a1.y, a1.z, a1.w};
      float bv[8] = {q0.x, q0.y, q0.z, q0.w, q1.x, q1.y, q1.z, q1.w};
#pragma unroll
      for (int i = 0; i < 8; ++i)
#pragma unroll
        for (int j = 0; j < 8; ++j) acc[i][j] = fmaf(av[i], bv[j], acc[i][j]);
    }
    __syncthreads();
  }

  const float4* bi4 = reinterpret_cast<const float4*>(b_ih);
  const float4* bh4 = reinterpret_cast<const float4*>(b_hh);
  int nb = (n0 >> 2) + tx;
  float4 u0 = bi4[nb], v0 = bh4[nb];
  float4 u1 = bi4[nb + 16], v1 = bh4[nb + 16];
  float4 bias0 = make_float4(u0.x + v0.x, u0.y + v0.y, u0.z + v0.z, u0.w + v0.w);
  float4 bias1 = make_float4(u1.x + v1.x, u1.y + v1.y, u1.z + v1.z, u1.w + v1.w);

#pragma unroll
  for (int hm = 0; hm < 2; ++hm)
#pragma unroll
    for (int i = 0; i < 4; ++i) {
      int m = m0 + hm * 64 + ty * 4 + i;
      int mi = hm * 4 + i;
      float* dst = &g_xg[(size_t)m * NG + n0];
      float4 o0 = make_float4(acc[mi][0] + bias0.x, acc[mi][1] + bias0.y,
                              acc[mi][2] + bias0.z, acc[mi][3] + bias0.w);
      float4 o1 = make_float4(acc[mi][4] + bias1.x, acc[mi][5] + bias1.y,
                              acc[mi][6] + bias1.z, acc[mi][7] + bias1.w);
      *reinterpret_cast<float4*>(&dst[tx * 4]) = o0;
      *reinterpret_cast<float4*>(&dst[64 + tx * 4]) = o1;
    }
}

// ---------------------------------------------------------------------------
// Phase 2: persistent recurrence with REGISTER-RESIDENT W (crossbar relief).
// 128 CTAs (1/SM), 256 threads. CTA = (j-block of 16) x (b-block of 16):
// 64 gate-rows (jl*4+g), rows n = g*512 + j0 + jl of w_hh.
//   - W slice (64 rows x 512 k fp32, 128 KB) lives in REGISTERS: warp wr owns
//     rows wr*8..+7; lane owns k-chunk [lane*16, lane*16+16) -> 64 u64 k-pairs
//     per thread, loaded from global ONCE. W never touches smem again.
//   - per step, only h (16 x 512 = 32 KB) is staged in smem (memcpy from out).
//   - per batch-row b: 4x LDS.128 h-pairs, 64 fully-unrolled FFMA2 against
//     register W (8 rows x 8 k-pairs), collapse, 3-level reduce-scatter
//     butterfly + 2 allreduce SHFLs over the 32 k-lanes; lanes 0..7 write the
//     8 finished gate values to gsm.
//   - activation: one (b,j) output per thread, c in a register.
//   - per-b-block grid barrier (4 independent groups of 32 CTAs).
// ---------------------------------------------------------------------------
__global__ __launch_bounds__(REC_THREADS, 1) void lstm_rec_kernel(
    const float* __restrict__ h0, const float* __restrict__ c0,
    const float* __restrict__ w_hh, float* __restrict__ out) {
  extern __shared__ float sm[];
  float* hsm = sm;                  // 16 rows x 512 k = 8192 floats
  float* gsm = sm + 8192;           // 16 b x 64 rows = 1024 floats

  const int tid = threadIdx.x;
  const int lane = tid & 31;
  const int wr = tid >> 5;           // warp 0..7 -> rows wr*8..+7
  const int jblk = blockIdx.x & 31;  // 32 j-blocks
  const int bblk = blockIdx.x >> 5;  // 4 b-blocks
  const int j0 = jblk * 16;
  const int b0 = bblk * 16;
  unsigned* bar = &g_arrive[bblk];

  // ---- load this thread's W slice into registers (once) ----
  // Wreg[r8*8 + p] = w_hh[n][lane*16 + 2p .. +1], n = g*512 + j0 + jl,
  // local row r = wr*8 + r8 = jl*4 + g.
  unsigned long long Wreg[64];
#pragma unroll
  for (int r8 = 0; r8 < 8; ++r8) {
    const int r = wr * 8 + r8;
    const int jl = r >> 2, g = r & 3;
    const float* rowp = w_hh + (size_t)(g * HH + j0 + jl) * HH + lane * 16;
#pragma unroll
    for (int q = 0; q < 4; ++q) {
      float4 v = *reinterpret_cast<const float4*>(rowp + q * 4);
      Wreg[r8 * 8 + q * 2 + 0] = pack2(v.x, v.y);
      Wreg[r8 * 8 + q * 2 + 1] = pack2(v.z, v.w);
    }
  }

  const uint32_t hsm_u32 = (uint32_t)__cvta_generic_to_shared(hsm);

  // value index owned after the reduce-scatter butterfly
  const int vown = ((lane & 1) << 2) | (lane & 2) | ((lane >> 2) & 1);
  const bool writer = (lane & 24) == 0;

  // activation-phase role: one (b,j) output per thread
  const int jl_o = tid & 15;
  const int bl_o = tid >> 4;
  const int b_o = b0 + bl_o;
  const int j_o = j0 + jl_o;

  float creg = c0[(size_t)b_o * HH + j_o];

  float* hf = out + (size_t)TT * BB_ * HH;
  float* cf = hf + (size_t)BB_ * HH;

  for (int t = 0; t < TT; ++t) {
    // stage this CTA's 16 h rows (contiguous) into smem
    const float* hsrc = (t == 0)
        ? (h0 + (size_t)b0 * HH)
        : (out + (size_t)(t - 1) * BB_ * HH + (size_t)b0 * HH);
    const float4* hs4 = reinterpret_cast<const float4*>(hsrc);
    float4* hd4 = reinterpret_cast<float4*>(hsm);
#pragma unroll
    for (int r = 0; r < 8; ++r)
      hd4[tid + r * REC_THREADS] = hs4[tid + r * REC_THREADS];

    // prefetch this thread's xg gates (hides DRAM latency behind the dot)
    const float* xrow = g_xg + ((size_t)t * BB_ + b_o) * NG + j_o;
    float xg0 = xrow[0];
    float xg1 = xrow[HH];
    float xg2 = xrow[2 * HH];
    float xg3 = xrow[3 * HH];

    __syncthreads();

    // ---- dot: 16 batch rows, register-resident W ----
#pragma unroll 1
    for (int b = 0; b < 16; ++b) {
      unsigned long long hv[8];
      const uint32_t ha = hsm_u32 + (uint32_t)(b * HH + lane * 16) * 4u;
      lds_v2u64(hv[0], hv[1], ha);
      lds_v2u64(hv[2], hv[3], ha + 16u);
      lds_v2u64(hv[4], hv[5], ha + 32u);
      lds_v2u64(hv[6], hv[7], ha + 48u);

      unsigned long long acc[8];
#pragma unroll
      for (int r8 = 0; r8 < 8; ++r8) acc[r8] = 0ull;
#pragma unroll
      for (int r8 = 0; r8 < 8; ++r8)
#pragma unroll
        for (int p = 0; p < 8; ++p) fma2(acc[r8], hv[p], Wreg[r8 * 8 + p]);

      float s[8];
#pragma unroll
      for (int r8 = 0; r8 < 8; ++r8) {
        float2 f = unpack2(acc[r8]);
        s[r8] = f.x + f.y;
      }

      // 3-level reduce-scatter butterfly (8 values -> 1 per lane), then
      // 2 allreduce SHFLs over lane bits 3,4 (k-split halves).
      {
        const bool u1 = (lane & 1) != 0;
#pragma unroll
        for (int i = 0; i < 4; ++i) {
          float send = u1 ? s[i] : s[i + 4];
          float recv = __shfl_xor_sync(0xffffffffu, send, 1);
          float keep = u1 ? s[i + 4] : s[i];
          s[i] = keep + recv;
        }
        const bool u2 = (lane & 2) != 0;
#pragma unroll
        for (int i = 0; i < 2; ++i) {
          float send = u2 ? s[i] : s[i + 2];
          float recv = __shfl_xor_sync(0xffffffffu, send, 2);
          float keep = u2 ? s[i + 2] : s[i];
          s[i] = keep + recv;
        }
        const bool u3 = (lane & 4) != 0;
        {
          float send = u3 ? s[0] : s[1];
          float recv = __shfl_xor_sync(0xffffffffu, send, 4);
          float keep = u3 ? s[1] : s[0];
          s[0] = keep + recv;
        }
        s[0] += __shfl_xor_sync(0xffffffffu, s[0], 8);
        s[0] += __shfl_xor_sync(0xffffffffu, s[0], 16);
      }

      if (writer) gsm[b * 64 + wr * 8 + vown] = s[0];
    }
    __syncthreads();

    // ---- gate math: one output per thread, c stays in a register ----
    {
      // gsm row layout: [b][jl*4 + g]
      float4 gv = *reinterpret_cast<const float4*>(&gsm[(bl_o * 16 + jl_o) * 4]);
      float ig = fast_sigmoid(gv.x + xg0);
      float fg = fast_sigmoid(gv.y + xg1);
      float tg = fast_tanh(gv.z + xg2);
      float og = fast_sigmoid(gv.w + xg3);
      float c = fg * creg + ig * tg;
      creg = c;
      float h = og * fast_tanh(c);

      out[(size_t)t * BB_ * HH + (size_t)b_o * HH + j_o] = h;
      if (t == TT - 1) {
        hf[(size_t)b_o * HH + j_o] = h;
        cf[(size_t)b_o * HH + j_o] = c;
      }
    }

    // per-b-block grid barrier (32 CTAs share a counter; all resident)
    if (t != TT - 1) {
      __threadfence();
      __syncthreads();
      if (tid == 0) {
        atomicAdd(bar, 1u);
        const unsigned target = (unsigned)(t + 1) * 32u;
        while (ld_acq_gpu(bar) < target) {
        }
      }
      __syncthreads();
    }
  }
}

extern "C" void kernel_launch(void* const* d_in, const int* in_sizes, int n_in,
                              void* d_out, int out_size) {
  (void)in_sizes; (void)n_in; (void)out_size;
  const float* x    = (const float*)d_in[0];
  const float* h0   = (const float*)d_in[1];
  const float* c0   = (const float*)d_in[2];
  const float* w_ih = (const float*)d_in[3];
  const float* w_hh = (const float*)d_in[4];
  const float* b_ih = (const float*)d_in[5];
  const float* b_hh = (const float*)d_in[6];
  float* out = (float*)d_out;

  cudaFuncSetAttribute(lstm_rec_kernel,
                       cudaFuncAttributeMaxDynamicSharedMemorySize, REC_SMEM);

  // Phase 1: input projection for all timesteps (also resets barrier state)
  xg_gemm_kernel<<<dim3(NG / 128, (TT * BB_) / 128), 256>>>(x, w_ih, b_ih, b_hh);
  // Phase 2: persistent recurrence with register-resident W
  lstm_rec_kernel<<<NCTA_REC, REC_THREADS, REC_SMEM>>>(h0, c0, w_hh, out);
}

// round 13
// speedup vs baseline: 1.2716x; 1.2716x over previous
#include <cuda_runtime.h>
#include <cstdint>

#define TT 512
#define BB_ 64
#define HH 512
#define II 256
#define NG 2048  // 4*H

#define NCTA_REC 128
#define REC_THREADS 256
#define REC_SMEM ((32768 + 8192 + 1024) * 4)  // W(128KB) + h(32KB) + gates(4KB)

// 256 MB scratch for the precomputed input projection (sanctioned __device__ scratch).
__device__ float g_xg[(size_t)TT * BB_ * NG];
// 16 quarter-barrier counters: [bblk(4)][quarter(4)], 32 arrivals per step each.
__device__ unsigned g_arrive[16];

static __device__ __forceinline__ unsigned ld_acq_gpu(unsigned* p) {
  unsigned v;
  asm volatile("ld.acquire.gpu.u32 %0, [%1];" : "=r"(v) : "l"(p) : "memory");
  return v;
}

static __device__ __forceinline__ void bar_sync(int id, int cnt) {
  asm volatile("bar.sync %0, %1;" :: "r"(id), "r"(cnt) : "memory");
}

static __device__ __forceinline__ float fast_sigmoid(float x) {
  return __fdividef(1.0f, 1.0f + __expf(-x));
}
static __device__ __forceinline__ float fast_tanh(float x) {
  float ax = fabsf(x);
  float e = __expf(-2.0f * ax);
  float r = __fdividef(1.0f - e, 1.0f + e);
  return copysignf(r, x);
}

// Packed dual-fp32 FMA (FFMA2): d = a*b + d elementwise on (lo,hi) pairs.
static __device__ __forceinline__ void fma2(unsigned long long& d,
                                            unsigned long long a,
                                            unsigned long long b) {
  asm("fma.rn.f32x2 %0, %1, %2, %0;" : "+l"(d) : "l"(a), "l"(b));
}

static __device__ __forceinline__ float2 unpack2(unsigned long long x) {
  float2 f;
  asm("mov.b64 {%0, %1}, %2;" : "=f"(f.x), "=f"(f.y) : "l"(x));
  return f;
}

static __device__ __forceinline__ unsigned long long dup2(float x) {
  unsigned long long r;
  asm("mov.b64 %0, {%1, %1};" : "=l"(r) : "f"(x));
  return r;
}

// 128-bit shared load straight into two b64 (k,k+1) pairs — no pack movs.
static __device__ __forceinline__ void lds_v2u64(unsigned long long& a,
                                                 unsigned long long& b,
                                                 uint32_t addr) {
  asm("ld.shared.v2.u64 {%0, %1}, [%2];" : "=l"(a), "=l"(b) : "r"(addr));
}

// ---------------------------------------------------------------------------
// Phase 1: xg[t*B+b, n] = sum_k x[t,b,k] * w_ih[n,k] + b_ih[n] + b_hh[n]
// 128x128x16 SGEMM tile, 256 threads, 8x8 micro-tile, FFMA2 inner product
// (acc packed along n-pairs; a broadcast-duplicated, b loaded as u64 pairs).
// Also resets the quarter-barrier counters for graph-replay determinism.
// ---------------------------------------------------------------------------
__global__ __launch_bounds__(256) void xg_gemm_kernel(
    const float* __restrict__ x, const float* __restrict__ w_ih,
    const float* __restrict__ b_ih, const float* __restrict__ b_hh) {
  if (blockIdx.x == 0 && blockIdx.y == 0 && threadIdx.x < 16)
    g_arrive[threadIdx.x] = 0u;

  __shared__ float Asm[16][132];
  __shared__ float Bsm[16][132];

  const int tid = threadIdx.x;
  const int tx = tid & 15;
  const int ty = tid >> 4;
  const int m0 = blockIdx.y * 128;
  const int n0 = blockIdx.x * 128;

  unsigned long long acc2[8][4];  // [m-row][n-pair]
#pragma unroll
  for (int i = 0; i < 8; ++i)
#pragma unroll
    for (int j = 0; j < 4; ++j) acc2[i][j] = 0ull;

  for (int k0 = 0; k0 < II; k0 += 16) {
#pragma unroll
    for (int r = 0; r < 2; ++r) {
      int idx = tid + r * 256;      // 0..511
      int m = idx >> 2;             // 0..127
      int kq = idx & 3;             // float4 within 16-wide k slab
      float4 v = *reinterpret_cast<const float4*>(
          &x[(size_t)(m0 + m) * II + k0 + kq * 4]);
      Asm[kq * 4 + 0][m] = v.x; Asm[kq * 4 + 1][m] = v.y;
      Asm[kq * 4 + 2][m] = v.z; Asm[kq * 4 + 3][m] = v.w;
      float4 w = *reinterpret_cast<const float4*>(
          &w_ih[(size_t)(n0 + m) * II + k0 + kq * 4]);
      Bsm[kq * 4 + 0][m] = w.x; Bsm[kq * 4 + 1][m] = w.y;
      Bsm[kq * 4 + 2][m] = w.z; Bsm[kq * 4 + 3][m] = w.w;
    }
    __syncthreads();
#pragma unroll
    for (int kk = 0; kk < 16; ++kk) {
      float4 a0 = *reinterpret_cast<const float4*>(&Asm[kk][ty * 4]);
      float4 a1 = *reinterpret_cast<const float4*>(&Asm[kk][64 + ty * 4]);
      // Bsm rows are 132 floats = 528B (16B-aligned); tx*16B offset aligned.
      ulonglong2 bq0 = *reinterpret_cast<const ulonglong2*>(&Bsm[kk][tx * 4]);
      ulonglong2 bq1 = *reinterpret_cast<const ulonglong2*>(&Bsm[kk][64 + tx * 4]);
      unsigned long long bp[4] = {bq0.x, bq0.y, bq1.x, bq1.y};
      float av[8] = {a0.x, a0.y, a0.z, a0.w, a1.x, a1.y, a1.z, a1.w};
#pragma unroll
      for (int i = 0; i < 8; ++i) {
        unsigned long long aa = dup2(av[i]);
#pragma unroll
        for (int j = 0; j < 4; ++j) fma2(acc2[i][j], aa, bp[j]);
      }
    }
    __syncthreads();
  }

  const float4* bi4 = reinterpret_cast<const float4*>(b_ih);
  const float4* bh4 = reinterpret_cast<const float4*>(b_hh);
  int nb = (n0 >> 2) + tx;
  float4 u0 = bi4[nb], v0 = bh4[nb];
  float4 u1 = bi4[nb + 16], v1 = bh4[nb + 16];
  float4 bias0 = make_float4(u0.x + v0.x, u0.y + v0.y, u0.z + v0.z, u0.w + v0.w);
  float4 bias1 = make_float4(u1.x + v1.x, u1.y + v1.y, u1.z + v1.z, u1.w + v1.w);

#pragma unroll
  for (int hm = 0; hm < 2; ++hm)
#pragma unroll
    for (int i = 0; i < 4; ++i) {
      int m = m0 + hm * 64 + ty * 4 + i;
      int mi = hm * 4 + i;
      float* dst = &g_xg[(size_t)m * NG + n0];
      float2 p0 = unpack2(acc2[mi][0]);
      float2 p1 = unpack2(acc2[mi][1]);
      float2 p2 = unpack2(acc2[mi][2]);
      float2 p3 = unpack2(acc2[mi][3]);
      float4 o0 = make_float4(p0.x + bias0.x, p0.y + bias0.y,
                              p1.x + bias0.z, p1.y + bias0.w);
      float4 o1 = make_float4(p2.x + bias1.x, p2.y + bias1.y,
                              p3.x + bias1.z, p3.y + bias1.w);
      *reinterpret_cast<float4*>(&dst[tx * 4]) = o0;
      *reinterpret_cast<float4*>(&dst[64 + tx * 4]) = o1;
    }
}

// ---------------------------------------------------------------------------
// Phase 2: persistent recurrence — FOUR INDEPENDENT 64-THREAD PIPELINES/CTA.
// 128 CTAs (1/SM), 256 threads. CTA = (j-block of 16) x (b-block of 16).
// Pair p = warps {2p, 2p+1} owns batch-quarter rows 4p..4p+3 end to end:
//   - its own hsm rows, its own gate tiles (bt == p), its own gsm region,
//     its own act threads (tid 64p..64p+63), its own quarter-barrier counter.
//   - sync via bar.sync(1+p, 64); NO CTA-wide __syncthreads in the step loop.
// SMSP s hosts warps s and s+4 (two DIFFERENT pairs) -> when one pair spins
// on its quarter barrier / runs its serial reduce+act tail, the other pair's
// warp keeps the FMA pipe busy. Dot/butterfly/act bodies verbatim from the
// passing R5 kernel (FFMA2, k-pair packed).
// ---------------------------------------------------------------------------
__global__ __launch_bounds__(REC_THREADS, 1) void lstm_rec_kernel(
    const float* __restrict__ h0, const float* __restrict__ c0,
    const float* __restrict__ w_hh, float* __restrict__ out) {
  extern __shared__ float sm[];
  float* Wsm = sm;                   // 64 rows x 512 k = 32768 floats
  float* hsm = sm + 32768;           // 16 rows x 512 k = 8192 floats
  float* gsm = sm + 32768 + 8192;    // 256 outputs x 4 gates = 1024 floats

  const int tid = threadIdx.x;
  const int jblk = blockIdx.x & 31;  // 32 j-blocks
  const int bblk = blockIdx.x >> 5;  // 4 b-blocks
  const int j0 = jblk * 16;
  const int b0 = bblk * 16;

  const int pair = tid >> 6;         // 0..3
  const int ptid = tid & 63;         // 0..63 within pair
  unsigned* qbar = &g_arrive[bblk * 4 + pair];

  // --- load w_hh slice into smem: Wsm[(jl*4+g)*512 + k] (once) ---
  {
    const float4* w4 = reinterpret_cast<const float4*>(w_hh);
    float4* Wd = reinterpret_cast<float4*>(Wsm);
#pragma unroll
    for (int r = 0; r < 32; ++r) {
      int f4 = tid + r * REC_THREADS;  // 0..8191
      int row = f4 >> 7;               // jl*4+g, 0..63
      int col = f4 & 127;
      int jl = row >> 2, g = row & 3;
      Wd[f4] = w4[(size_t)(g * HH + j0 + jl) * (HH / 4) + col];
    }
  }

  const uint32_t hsm_u32 = (uint32_t)__cvta_generic_to_shared(hsm);
  const uint32_t wsm_u32 = (uint32_t)__cvta_generic_to_shared(Wsm);

  // dot-phase role: tid = tile*8 + ks ; tile = bt*8 + jt ; bt == pair
  const int ks = tid & 7;            // k-split lane (8-way)
  const int tile = tid >> 3;         // 0..31
  const int jt = tile & 7;           // 8 j-tiles of 2 rows (x4 gates)
  const int bt = tile >> 3;          // == pair

  // output owned after the 3-level reduce-scatter butterfly (R5 mapping)
  const int b_own = ((ks & 1) << 2) | (ks & 2) | ((ks >> 2) & 1);
  const int o_own = (bt * 8 + b_own) * 16 + jt;  // NOTE: bt*8+b_own in 0..7 range pairs
  // (R5 wrote o = (bt*4+i)*16 + jt*2+jj via per-i loop; here identical layout:
  //  gsm entry o = b_local*16 + j_local, b_local = bt*4 + (b_own>>1)? -- we
  //  keep the exact R5 write path below instead, computed per (i,jj).)

  // activation-phase role: one (b,j) output per thread; tid 64p..64p+63 owns
  // b rows 4p..4p+3 exactly (bl_o = tid>>4 in {4p..4p+3}).
  const int jl_o = tid & 15;
  const int bl_o = tid >> 4;
  const int b_o = b0 + bl_o;
  const int j_o = j0 + jl_o;

  float creg = c0[(size_t)b_o * HH + j_o];

  float* hf = out + (size_t)TT * BB_ * HH;
  float* cf = hf + (size_t)BB_ * HH;

  __syncthreads();  // W staged before any pair proceeds

  for (int t = 0; t < TT; ++t) {
    // prefetch this thread's xg gates (overlaps the spin + dot latency)
    const float* xrow = g_xg + ((size_t)t * BB_ + b_o) * NG + j_o;
    float xg0 = xrow[0];
    float xg1 = xrow[HH];
    float xg2 = xrow[2 * HH];
    float xg3 = xrow[3 * HH];

    // wait for this quarter's h(t-1) from all 32 CTAs of the b-group
    if (t > 0) {
      const unsigned target = (unsigned)t * 32u;
      while (ld_acq_gpu(qbar) < target) {
      }
    }

    // copy this pair's 4 h rows into hsm (8 float4 per thread, coalesced)
    {
      const float* hbase = (t == 0)
          ? (h0 + (size_t)b0 * HH)
          : (out + (size_t)(t - 1) * BB_ * HH + (size_t)b0 * HH);
      const float4* s4 = reinterpret_cast<const float4*>(hbase) + pair * 512;
      float4* d4 = reinterpret_cast<float4*>(hsm) + pair * 512;
#pragma unroll
      for (int r = 0; r < 8; ++r) d4[ptid + r * 64] = s4[ptid + r * 64];
    }
    bar_sync(1 + pair, 64);

    // ---- dot (verbatim R5 body; bt == pair) ----
    unsigned long long acc[32];  // [i(4 b-rows)][jj(2)][g(4)], k-pair packed
#pragma unroll
    for (int v = 0; v < 32; ++v) acc[v] = 0ull;

    const uint32_t hrow_base = hsm_u32 + (uint32_t)(bt * 4) * HH * 4u;
    const uint32_t wrow_base = wsm_u32 + (uint32_t)(jt * 2) * 4u * HH * 4u;

#pragma unroll 2
    for (int m = 0; m < 16; ++m) {
      const uint32_t kb = (uint32_t)(m * 32 + ks * 4);
      unsigned long long ha[4], hb[4];
#pragma unroll
      for (int i = 0; i < 4; ++i)
        lds_v2u64(ha[i], hb[i], hrow_base + (uint32_t)(i * HH + kb) * 4u);
#pragma unroll
      for (int jj = 0; jj < 2; ++jj)
#pragma unroll
        for (int g = 0; g < 4; ++g) {
          unsigned long long wa, wb;
          lds_v2u64(wa, wb, wrow_base + (uint32_t)((jj * 4 + g) * HH + kb) * 4u);
#pragma unroll
          for (int i = 0; i < 4; ++i) {
            fma2(acc[(i * 2 + jj) * 4 + g], ha[i], wa);
            fma2(acc[(i * 2 + jj) * 4 + g], hb[i], wb);
          }
        }
    }

    // collapse k-pairs, 3-level reduce-scatter over 8 ks lanes (R5 verbatim)
    float r[32];
#pragma unroll
    for (int v = 0; v < 32; ++v) {
      float2 f = unpack2(acc[v]);
      r[v] = f.x + f.y;
    }
    {
      const bool u1 = (ks & 1) != 0;
#pragma unroll
      for (int i = 0; i < 16; ++i) {
        float send = u1 ? r[i] : r[i + 16];
        float recv = __shfl_xor_sync(0xffffffffu, send, 1);
        float keep = u1 ? r[i + 16] : r[i];
        r[i] = keep + recv;
      }
      const bool u2 = (ks & 2) != 0;
#pragma unroll
      for (int i = 0; i < 8; ++i) {
        float send = u2 ? r[i] : r[i + 8];
        float recv = __shfl_xor_sync(0xffffffffu, send, 2);
        float keep = u2 ? r[i + 8] : r[i];
        r[i] = keep + recv;
      }
      const bool u3 = (ks & 4) != 0;
#pragma unroll
      for (int i = 0; i < 4; ++i) {
        float send = u3 ? r[i] : r[i + 4];
        float recv = __shfl_xor_sync(0xffffffffu, send, 4);
        float keep = u3 ? r[i + 4] : r[i];
        r[i] = keep + recv;
      }
    }
    // lane owns acc index group: r[0..3] = gates of (i_own, jj_own) where the
    // index layout is (i*2+jj): after 3 levels, owned flat index = the 3 kept
    // bits; R5 proved: lane ks owns (i,jj) with i*2+jj = b_own (0..7).
    {
      const int i_own = b_own >> 1;
      const int jj_own = b_own & 1;
      const int o = (bt * 4 + i_own) * 16 + jt * 2 + jj_own;
      *reinterpret_cast<float4*>(&gsm[o * 4]) =
          make_float4(r[0], r[1], r[2], r[3]);
    }
    bar_sync(1 + pair, 64);

    // ---- act: one output per thread (pair-local region of gsm) ----
    {
      float4 gv = *reinterpret_cast<const float4*>(&gsm[tid * 4]);
      float ig = fast_sigmoid(gv.x + xg0);
      float fg = fast_sigmoid(gv.y + xg1);
      float tg = fast_tanh(gv.z + xg2);
      float og = fast_sigmoid(gv.w + xg3);
      float c = fg * creg + ig * tg;
      creg = c;
      float h = og * fast_tanh(c);

      out[(size_t)t * BB_ * HH + (size_t)b_o * HH + j_o] = h;
      if (t == TT - 1) {
        hf[(size_t)b_o * HH + j_o] = h;
        cf[(size_t)b_o * HH + j_o] = c;
      }
    }

    // quarter-barrier arrive (this pair's 4 h rows are written)
    if (t != TT - 1) {
      __threadfence();
      bar_sync(1 + pair, 64);
      if (ptid == 0) atomicAdd(qbar, 1u);
    }
  }
}

extern "C" void kernel_launch(void* const* d_in, const int* in_sizes, int n_in,
                              void* d_out, int out_size) {
  (void)in_sizes; (void)n_in; (void)out_size;
  const float* x    = (const float*)d_in[0];
  const float* h0   = (const float*)d_in[1];
  const float* c0   = (const float*)d_in[2];
  const float* w_ih = (const float*)d_in[3];
  const float* w_hh = (const float*)d_in[4];
  const float* b_ih = (const float*)d_in[5];
  const float* b_hh = (const float*)d_in[6];
  float* out = (float*)d_out;

  cudaFuncSetAttribute(lstm_rec_kernel,
                       cudaFuncAttributeMaxDynamicSharedMemorySize, REC_SMEM);

  // Phase 1: input projection for all timesteps (also resets barrier state)
  xg_gemm_kernel<<<dim3(NG / 128, (TT * BB_) / 128), 256>>>(x, w_ih, b_ih, b_hh);
  // Phase 2: persistent recurrence, 4 decoupled pipelines per CTA
  lstm_rec_kernel<<<NCTA_REC, REC_THREADS, REC_SMEM>>>(h0, c0, w_hh, out);
}